// round 10
// baseline (speedup 1.0000x reference)
#include <cuda_runtime.h>
#include <cuda_bf16.h>
#include <math.h>

// Problem constants
#define B    256
#define T    2048
#define D    64
#define N    128
#define LEAK 0.5f

// 256MB scratch: u[b][t][n] = x[b,t,:]@W_in[:,n] + b_in[n], fp32
__device__ float g_u[(size_t)B * T * N];

// ---------------------------------------------------------------------------
// XLA ElementalIrEmitter::EmitTanh replica — VERIFIED BITWISE vs reference:
//   clamp 7.99881172180175781, |x|<0.0004 passthrough, contracted (FMA)
//   Horner for numerator/denominator, IEEE divide.
// ---------------------------------------------------------------------------
__device__ __forceinline__ float tanh_xla(float x) {
    const float kClamp = 7.99881172180175781f;
    const float kTiny  = 0.0004f;
    float cx = fminf(fmaxf(x, -kClamp), kClamp);
    float x2 = __fmul_rn(cx, cx);
    float p = -2.76076847742355e-16f;
    p = __fmaf_rn(x2, p, 2.00018790482477e-13f);
    p = __fmaf_rn(x2, p, -8.60467152213735e-11f);
    p = __fmaf_rn(x2, p, 5.12229709037114e-08f);
    p = __fmaf_rn(x2, p, 1.48572235717979e-05f);
    p = __fmaf_rn(x2, p, 6.37261928875436e-04f);
    p = __fmaf_rn(x2, p, 4.89352455891786e-03f);
    p = __fmul_rn(cx, p);
    float q = 1.19825839466702e-06f;
    q = __fmaf_rn(x2, q, 1.18534705686654e-04f);
    q = __fmaf_rn(x2, q, 2.26843463243900e-03f);
    q = __fmaf_rn(x2, q, 4.89352518554385e-03f);
    float r = __fdiv_rn(p, q);
    return (fabsf(x) < kTiny) ? x : r;
}

// ---------------------------------------------------------------------------
// Kernel 1: u[b][t][n] = (sum_{d ascending} fmaf(x[b,t,d], W_in[d,n], acc)) + b_in[n]
// Single sequential FMA chain per output (verified reference k-order).
// Grid (B, T/64), 128 threads (thread = n). W_in column in registers,
// x rows staged through SMEM, 4-row ILP.
// ---------------------------------------------------------------------------
__global__ __launch_bounds__(128) void uproj_kernel(
    const float* __restrict__ x,
    const float* __restrict__ W_in,
    const float* __restrict__ b_in)
{
    const int b  = blockIdx.x;
    const int t0 = blockIdx.y * 64;
    const int n  = threadIdx.x;
    const int tid = threadIdx.x;

    float w[D];
#pragma unroll
    for (int d = 0; d < D; d++) w[d] = W_in[d * N + n];
    const float bv = b_in[n];

    __shared__ __align__(16) float xs[4][D];

    const float* xrow = x + (size_t)b * T * D;
    float* uo = g_u + ((size_t)b * T + t0) * N + n;

    for (int blk = 0; blk < 16; blk++) {
        const int r0 = blk * 4;
#pragma unroll
        for (int j = tid; j < 4 * D; j += 128) {
            int r = j >> 6, d = j & (D - 1);
            xs[r][d] = xrow[(size_t)(t0 + r0 + r) * D + d];
        }
        __syncthreads();

        float acc0 = 0.f, acc1 = 0.f, acc2 = 0.f, acc3 = 0.f;
#pragma unroll
        for (int d = 0; d < D; d += 4) {
            float4 q0 = *reinterpret_cast<const float4*>(&xs[0][d]);
            float4 q1 = *reinterpret_cast<const float4*>(&xs[1][d]);
            float4 q2 = *reinterpret_cast<const float4*>(&xs[2][d]);
            float4 q3 = *reinterpret_cast<const float4*>(&xs[3][d]);
            acc0 = __fmaf_rn(q0.x, w[d], acc0);
            acc0 = __fmaf_rn(q0.y, w[d+1], acc0);
            acc0 = __fmaf_rn(q0.z, w[d+2], acc0);
            acc0 = __fmaf_rn(q0.w, w[d+3], acc0);
            acc1 = __fmaf_rn(q1.x, w[d], acc1);
            acc1 = __fmaf_rn(q1.y, w[d+1], acc1);
            acc1 = __fmaf_rn(q1.z, w[d+2], acc1);
            acc1 = __fmaf_rn(q1.w, w[d+3], acc1);
            acc2 = __fmaf_rn(q2.x, w[d], acc2);
            acc2 = __fmaf_rn(q2.y, w[d+1], acc2);
            acc2 = __fmaf_rn(q2.z, w[d+2], acc2);
            acc2 = __fmaf_rn(q2.w, w[d+3], acc2);
            acc3 = __fmaf_rn(q3.x, w[d], acc3);
            acc3 = __fmaf_rn(q3.y, w[d+1], acc3);
            acc3 = __fmaf_rn(q3.z, w[d+2], acc3);
            acc3 = __fmaf_rn(q3.w, w[d+3], acc3);
        }
        uo[(size_t)(r0+0)*N] = __fadd_rn(acc0, bv);
        uo[(size_t)(r0+1)*N] = __fadd_rn(acc1, bv);
        uo[(size_t)(r0+2)*N] = __fadd_rn(acc2, bv);
        uo[(size_t)(r0+3)*N] = __fadd_rn(acc3, bv);
        __syncthreads();
    }
}

// ---------------------------------------------------------------------------
// Kernel 2: sequential scan. Grid = 128 CTAs (one per batch pair),
// 256 threads: par = tid>>7, n = tid&127. Each thread owns W_res[:,n] in
// registers and computes the FULL 128-long ascending-k FMA chain (single
// accumulator) — verified reference semantics. State double-buffered in SMEM.
// ---------------------------------------------------------------------------
__global__ __launch_bounds__(256, 1) void scan_kernel(
    const float* __restrict__ W_res,
    const float* __restrict__ b_res,
    float* __restrict__ X)
{
    __shared__ __align__(16) float st[2][2][N];

    const int tid = threadIdx.x;
    const int par = tid >> 7;
    const int n   = tid & (N - 1);
    const int b   = 2 * blockIdx.x + par;

    float w[N];
#pragma unroll
    for (int k = 0; k < N; k++) w[k] = W_res[k * N + n];
    const float brv = b_res[n];

    const float* up = g_u + (size_t)b * T * N + n;
    float* xo = X + (size_t)b * T * N + n;

    // t = 0 : x0 = LEAK * tanh(u0)
    float u0 = up[0];
    float xv = __fmul_rn(LEAK, tanh_xla(u0));
    st[0][par][n] = xv;
    xo[0] = xv;
    float u_nxt = up[(size_t)1 * N];
    __syncthreads();

    for (int t = 1; t < T; t++) {
        const float ucur = u_nxt;
        int tn = (t + 1 < T) ? (t + 1) : t;
        u_nxt = up[(size_t)tn * N];

        const float* xp = st[(t - 1) & 1][par];
        float acc = 0.f;
#pragma unroll
        for (int k = 0; k < N; k += 4) {
            float4 qv = *reinterpret_cast<const float4*>(xp + k);
            acc = __fmaf_rn(qv.x, w[k],     acc);
            acc = __fmaf_rn(qv.y, w[k + 1], acc);
            acc = __fmaf_rn(qv.z, w[k + 2], acc);
            acc = __fmaf_rn(qv.w, w[k + 3], acc);
        }

        float arg = __fadd_rn(__fadd_rn(ucur, acc), brv);
        float th  = tanh_xla(arg);
        xv = __fadd_rn(__fmul_rn(1.0f - LEAK, xv), __fmul_rn(LEAK, th));

        st[t & 1][par][n] = xv;
        xo[(size_t)t * N] = xv;
        __syncthreads();
    }
}

// ---------------------------------------------------------------------------
extern "C" void kernel_launch(void* const* d_in, const int* in_sizes, int n_in,
                              void* d_out, int out_size)
{
    const float* x     = (const float*)d_in[0];
    const float* W_in  = (const float*)d_in[1];
    const float* b_in  = (const float*)d_in[2];
    const float* W_res = (const float*)d_in[3];
    const float* b_res = (const float*)d_in[4];
    float* X = (float*)d_out;

    dim3 gc(B, T / 64);
    uproj_kernel<<<gc, 128>>>(x, W_in, b_in);
    scan_kernel<<<B / 2, 256>>>(W_res, b_res, X);
}

// round 11
// speedup vs baseline: 1.2114x; 1.2114x over previous
#include <cuda_runtime.h>
#include <cuda_bf16.h>
#include <math.h>

// Problem constants
#define B    256
#define T    2048
#define D    64
#define N    128
#define LEAK 0.5f

// 256MB scratch: u[b][t][n] = x[b,t,:]@W_in[:,n] + b_in[n], fp32
__device__ float g_u[(size_t)B * T * N];

// ---------------- f32x2 helpers (per-lane IEEE fp32 — bitwise-safe) ----------
__device__ __forceinline__ unsigned long long pack2(float lo, float hi) {
    unsigned long long r;
    asm("mov.b64 %0, {%1, %2};" : "=l"(r) : "f"(lo), "f"(hi));
    return r;
}
__device__ __forceinline__ void unpack2(unsigned long long v, float& lo, float& hi) {
    asm("mov.b64 {%0, %1}, %2;" : "=f"(lo), "=f"(hi) : "l"(v));
}
__device__ __forceinline__ unsigned long long ffma2(unsigned long long a,
                                                    unsigned long long b,
                                                    unsigned long long c) {
    unsigned long long d;
    asm("fma.rn.f32x2 %0, %1, %2, %3;" : "=l"(d) : "l"(a), "l"(b), "l"(c));
    return d;
}

// ---------------------------------------------------------------------------
// XLA ElementalIrEmitter::EmitTanh replica — VERIFIED BITWISE vs reference:
//   clamp 7.99881172180175781, |x|<0.0004 passthrough, contracted (FMA)
//   Horner for numerator/denominator, IEEE divide.
// ---------------------------------------------------------------------------
__device__ __forceinline__ float tanh_xla(float x) {
    const float kClamp = 7.99881172180175781f;
    const float kTiny  = 0.0004f;
    float cx = fminf(fmaxf(x, -kClamp), kClamp);
    float x2 = __fmul_rn(cx, cx);
    float p = -2.76076847742355e-16f;
    p = __fmaf_rn(x2, p, 2.00018790482477e-13f);
    p = __fmaf_rn(x2, p, -8.60467152213735e-11f);
    p = __fmaf_rn(x2, p, 5.12229709037114e-08f);
    p = __fmaf_rn(x2, p, 1.48572235717979e-05f);
    p = __fmaf_rn(x2, p, 6.37261928875436e-04f);
    p = __fmaf_rn(x2, p, 4.89352455891786e-03f);
    p = __fmul_rn(cx, p);
    float q = 1.19825839466702e-06f;
    q = __fmaf_rn(x2, q, 1.18534705686654e-04f);
    q = __fmaf_rn(x2, q, 2.26843463243900e-03f);
    q = __fmaf_rn(x2, q, 4.89352518554385e-03f);
    float r = __fdiv_rn(p, q);
    return (fabsf(x) < kTiny) ? x : r;
}

// ---------------------------------------------------------------------------
// Kernel 1: u = chain-gemm(x, W_in) + b_in, f32x2 row-pair packed.
// Lane0 = row 2r, lane1 = row 2r+1; per-lane chain == verified scalar chain.
// Grid (B, T/64), 128 threads (thread = n). W_in column duplicated into
// f32x2 registers; 8 rows (4 pairs) staged per block iteration.
// ---------------------------------------------------------------------------
__global__ __launch_bounds__(128) void uproj_kernel(
    const float* __restrict__ x,
    const float* __restrict__ W_in,
    const float* __restrict__ b_in)
{
    const int b  = blockIdx.x;
    const int t0 = blockIdx.y * 64;
    const int n  = threadIdx.x;
    const int tid = threadIdx.x;

    unsigned long long w2[D];          // 64 u64 = 128 regs
#pragma unroll
    for (int d = 0; d < D; d++) {
        float v = W_in[d * N + n];
        w2[d] = pack2(v, v);
    }
    const float bv = b_in[n];

    __shared__ __align__(16) unsigned long long xs2[4][D];   // 4 row-pairs

    const float* xrow = x + (size_t)b * T * D;
    float* uo = g_u + ((size_t)b * T + t0) * N + n;

    for (int blk = 0; blk < 8; blk++) {
        const int r0 = blk * 8;        // 8 rows = 4 pairs per iteration
        // stage: 128 threads -> tid = p*64 + d, p in {0,1}; pairs p and p+2
        {
            int p = tid >> 6, d = tid & (D - 1);
#pragma unroll
            for (int s = 0; s < 2; s++) {
                int pr = p + 2 * s;
                float lo = xrow[(size_t)(t0 + r0 + 2 * pr)     * D + d];
                float hi = xrow[(size_t)(t0 + r0 + 2 * pr + 1) * D + d];
                xs2[pr][d] = pack2(lo, hi);
            }
        }
        __syncthreads();

        unsigned long long a0 = 0ull, a1 = 0ull, a2 = 0ull, a3 = 0ull;
#pragma unroll
        for (int d = 0; d < D; d += 2) {
            ulonglong2 q0 = *reinterpret_cast<const ulonglong2*>(&xs2[0][d]);
            ulonglong2 q1 = *reinterpret_cast<const ulonglong2*>(&xs2[1][d]);
            ulonglong2 q2 = *reinterpret_cast<const ulonglong2*>(&xs2[2][d]);
            ulonglong2 q3 = *reinterpret_cast<const ulonglong2*>(&xs2[3][d]);
            a0 = ffma2(q0.x, w2[d], a0);  a0 = ffma2(q0.y, w2[d + 1], a0);
            a1 = ffma2(q1.x, w2[d], a1);  a1 = ffma2(q1.y, w2[d + 1], a1);
            a2 = ffma2(q2.x, w2[d], a2);  a2 = ffma2(q2.y, w2[d + 1], a2);
            a3 = ffma2(q3.x, w2[d], a3);  a3 = ffma2(q3.y, w2[d + 1], a3);
        }
        float s0, s1;
        unpack2(a0, s0, s1);
        uo[(size_t)(r0 + 0) * N] = __fadd_rn(s0, bv);
        uo[(size_t)(r0 + 1) * N] = __fadd_rn(s1, bv);
        unpack2(a1, s0, s1);
        uo[(size_t)(r0 + 2) * N] = __fadd_rn(s0, bv);
        uo[(size_t)(r0 + 3) * N] = __fadd_rn(s1, bv);
        unpack2(a2, s0, s1);
        uo[(size_t)(r0 + 4) * N] = __fadd_rn(s0, bv);
        uo[(size_t)(r0 + 5) * N] = __fadd_rn(s1, bv);
        unpack2(a3, s0, s1);
        uo[(size_t)(r0 + 6) * N] = __fadd_rn(s0, bv);
        uo[(size_t)(r0 + 7) * N] = __fadd_rn(s1, bv);
        __syncthreads();
    }
}

// ---------------------------------------------------------------------------
// Kernel 2: sequential scan. Grid = 128 CTAs (one per batch pair),
// 256 threads: par = tid>>7, n = tid&127. The two par-groups NEVER share
// state (st[buf][par][*] is produced and consumed only by par's 4 warps),
// so each group syncs with its own named barrier (ids 1,2) — cheaper and
// decoupled. Chain uses an explicit depth-4 rotating float4 prefetch so
// LDS latency (29cyc) is fully hidden behind the FMA chain (16cyc/float4).
// Output STG moved off the critical path (after the barrier).
// ---------------------------------------------------------------------------
__global__ __launch_bounds__(256, 1) void scan_kernel(
    const float* __restrict__ W_res,
    const float* __restrict__ b_res,
    float* __restrict__ X)
{
    __shared__ __align__(16) float st[2][2][N];

    const int tid = threadIdx.x;
    const int par = tid >> 7;
    const int n   = tid & (N - 1);
    const int b   = 2 * blockIdx.x + par;
    const int barid = par + 1;          // named barrier 1 or 2

    float w[N];
#pragma unroll
    for (int k = 0; k < N; k++) w[k] = W_res[k * N + n];
    const float brv = b_res[n];

    const float* up = g_u + (size_t)b * T * N + n;
    float* xo = X + (size_t)b * T * N + n;

    // t = 0 : x0 = LEAK * tanh(u0)
    float u0 = up[0];
    float xv = __fmul_rn(LEAK, tanh_xla(u0));
    st[0][par][n] = xv;
    xo[0] = xv;
    float u_nxt = up[(size_t)1 * N];
    asm volatile("bar.sync %0, %1;" :: "r"(barid), "r"(128) : "memory");

    for (int t = 1; t < T; t++) {
        const float ucur = u_nxt;
        int tn = (t + 1 < T) ? (t + 1) : t;
        u_nxt = up[(size_t)tn * N];

        const float4* xp4 =
            reinterpret_cast<const float4*>(st[(t - 1) & 1][par]);

        // depth-4 rotating prefetch: loads run >=64cyc ahead of consumption
        float4 f0 = xp4[0];
        float4 f1 = xp4[1];
        float4 f2 = xp4[2];
        float4 f3 = xp4[3];
        float acc = 0.f;
#pragma unroll
        for (int j = 0; j < 32; j++) {
            float4 c = f0;
            f0 = f1; f1 = f2; f2 = f3;
            if (j < 28) f3 = xp4[j + 4];
            acc = __fmaf_rn(c.x, w[4 * j],     acc);
            acc = __fmaf_rn(c.y, w[4 * j + 1], acc);
            acc = __fmaf_rn(c.z, w[4 * j + 2], acc);
            acc = __fmaf_rn(c.w, w[4 * j + 3], acc);
        }

        float arg = __fadd_rn(__fadd_rn(ucur, acc), brv);
        float th  = tanh_xla(arg);
        xv = __fadd_rn(__fmul_rn(1.0f - LEAK, xv), __fmul_rn(LEAK, th));

        st[t & 1][par][n] = xv;
        asm volatile("bar.sync %0, %1;" :: "r"(barid), "r"(128) : "memory");
        xo[(size_t)t * N] = xv;          // off the serial path
    }
}

// ---------------------------------------------------------------------------
extern "C" void kernel_launch(void* const* d_in, const int* in_sizes, int n_in,
                              void* d_out, int out_size)
{
    const float* x     = (const float*)d_in[0];
    const float* W_in  = (const float*)d_in[1];
    const float* b_in  = (const float*)d_in[2];
    const float* W_res = (const float*)d_in[3];
    const float* b_res = (const float*)d_in[4];
    float* X = (float*)d_out;

    dim3 gc(B, T / 64);
    uproj_kernel<<<gc, 128>>>(x, W_in, b_in);
    scan_kernel<<<B / 2, 256>>>(W_res, b_res, X);
}